// round 11
// baseline (speedup 1.0000x reference)
#include <cuda_runtime.h>

#define NB 4
#define NXg 432
#define NYg 496
#define Hc 248
#define Wc 216
#define HW (Hc*Wc)            // 53568
#define C1 8
#define C2 16
#define COUT 400
#define CSP 384
#define KS 15
#define RAD 7
#define NBN (NB*HW)
#define GTOT (NB*NYg*NXg)     // 857088

#define NBLK 592              // = 148 SMs * 4 blocks (all co-resident)
#define TPB  256
#define NTH  (NBLK*TPB)       // 151552 threads

#define COPY_N (NB*CSP*HW/4)  // 20,570,112 float4
#define PER_B  (CSP*HW/4)     // 5,142,528
#define DSKIP  ((COUT-CSP)*HW/4)

// copy chunk boundaries per stage (cumulative float4 indices)
#define E1 2900000
#define E2 5900000
#define E3 8900000
#define E4 12100000
#define E5 15100000
#define E6 16300000
// stage 7 copies [E6, COPY_N)

// conv tiling: one (channel, segment) tile per block, 576 tiles
#define SEG1 18
#define PX1  (HW/SEG1)        // 2976
#define SEG2 9
#define PX2  (HW/SEG2)        // 5952

// scratch (device globals; zero-initialized at load)
__device__ float g_hist[GTOT];     // zeroed at end of each launch for the next
__device__ float g_tmp [GTOT];
__device__ float g_dm  [NB*HW];
__device__ float g_c1  [NB*C1*HW];
__device__ float g_c2  [NB*C2*HW];
__device__ float g_gauss[KS];
__device__ int   g_max[NB];
__device__ float g_stats1[2*C1];
__device__ float g_stats2[2*C2];
// barrier state (self-restoring: even # of barriers per launch)
__device__ int          g_cnt;
__device__ volatile int g_sense;

__device__ __forceinline__ void copy_range(const float4* __restrict__ src,
                                           float4* __restrict__ dst,
                                           int start, int end, int t) {
    for (int i = start + t; i < end; i += 4*NTH) {
        int i1 = i + NTH, i2 = i + 2*NTH, i3 = i + 3*NTH;
        bool p1 = i1 < end, p2 = i2 < end, p3 = i3 < end;
        float4 v0, v1, v2, v3;
        v0 = __ldcs(src + i);
        if (p1) v1 = __ldcs(src + i1);
        if (p2) v2 = __ldcs(src + i2);
        if (p3) v3 = __ldcs(src + i3);
        __stcs(dst + i  + (i /PER_B)*DSKIP, v0);
        if (p1) __stcs(dst + i1 + (i1/PER_B)*DSKIP, v1);
        if (p2) __stcs(dst + i2 + (i2/PER_B)*DSKIP, v2);
        if (p3) __stcs(dst + i3 + (i3/PER_B)*DSKIP, v3);
    }
}

// antialiased bilinear 2x down taps: [1,3,3,1], edge-clipped + renormalized
__device__ __forceinline__ void taps4(int i, int n, int* j, float* w) {
    const float base[4] = {1.f, 3.f, 3.f, 1.f};
    float s = 0.f;
    #pragma unroll
    for (int k = 0; k < 4; k++) {
        int jj = 2*i - 1 + k;
        j[k] = jj;
        if (jj >= 0 && jj < n) { w[k] = base[k]; s += base[k]; }
        else w[k] = 0.f;
    }
    #pragma unroll
    for (int k = 0; k < 4; k++) w[k] /= s;
}

__global__ void __launch_bounds__(TPB, 4)
k_all(const float* __restrict__ pts, int npts,
      const float* __restrict__ w1, const float* __restrict__ gamma1, const float* __restrict__ beta1,
      const float* __restrict__ w2, const float* __restrict__ gamma2, const float* __restrict__ beta2,
      const float4* __restrict__ csrc, float4* __restrict__ cdst, float* __restrict__ out)
{
    const int bid = blockIdx.x;
    const int t   = bid*TPB + threadIdx.x;

    __shared__ float sm1[TPB], sm2[TPB];
    __shared__ float ws[C1*9];
    __shared__ float sA[C2], sB[C2];
    __shared__ int   lsense;
    if (threadIdx.x == 0) lsense = 0;
    __syncthreads();

    auto gbar = [&]() {
        __syncthreads();
        if (threadIdx.x == 0) {
            int s = lsense ^ 1; lsense = s;
            __threadfence();
            if (atomicAdd(&g_cnt, 1) == NBLK - 1) {
                g_cnt = 0;
                g_sense = s;
            } else {
                while (g_sense != s) __nanosleep(64);
            }
            __threadfence();
        }
        __syncthreads();
    };

    // ---- s1: init (gauss, zero stats/max) + histogram ----
    if (t < KS) {
        const float sig = 6.25f;
        float s = 0.f;
        for (int k = 0; k < KS; k++) {
            float c = (float)(k - RAD);
            s += expf(-c*c/(2.f*sig*sig));
        }
        float c = (float)(t - RAD);
        g_gauss[t] = expf(-c*c/(2.f*sig*sig)) / s;
    }
    if (t < NB)   g_max[t] = 0;
    if (t < 2*C1) g_stats1[t] = 0.f;
    if (t < 2*C2) g_stats2[t] = 0.f;
    for (int i = t; i < npts; i += NTH) {
        const float* p = pts + (size_t)i*5;
        int b = (int)p[0];
        int x = (int)__fdiv_rn(p[1] - 0.0f,  0.16f);
        int y = (int)__fdiv_rn(p[2] + 39.68f, 0.16f);
        x = min(max(x, 0), NXg-1);
        y = min(max(y, 0), NYg-1);
        atomicAdd(&g_hist[(b*NYg + y)*NXg + x], 1.0f);   // g_hist pre-zeroed
    }
    copy_range(csrc, cdst, 0, E1, t);
    gbar(); // 1

    // ---- s2: blur x ----
    for (int i = t; i < GTOT; i += NTH) {
        int x = i % NXg;
        int row = i / NXg;
        float acc = 0.f;
        #pragma unroll
        for (int k = 0; k < KS; k++) {
            int xx = x + k - RAD;
            if (xx >= 0 && xx < NXg)
                acc += g_gauss[k] * g_hist[row*NXg + xx];
        }
        g_tmp[i] = acc;
    }
    copy_range(csrc, cdst, E1, E2, t);
    gbar(); // 2

    // ---- s3: blur y + per-batch max ----
    {
        float m0 = 0.f, m1 = 0.f, m2 = 0.f, m3 = 0.f;
        for (int i = t; i < GTOT; i += NTH) {
            int x = i % NXg;
            int y = (i / NXg) % NYg;
            int b = i / (NXg*NYg);
            float acc = 0.f;
            #pragma unroll
            for (int k = 0; k < KS; k++) {
                int yy = y + k - RAD;
                if (yy >= 0 && yy < NYg)
                    acc += g_gauss[k] * g_tmp[(b*NYg + yy)*NXg + x];
            }
            g_hist[i] = acc;
            m0 = (b == 0) ? fmaxf(m0, acc) : m0;
            m1 = (b == 1) ? fmaxf(m1, acc) : m1;
            m2 = (b == 2) ? fmaxf(m2, acc) : m2;
            m3 = (b == 3) ? fmaxf(m3, acc) : m3;
        }
        #pragma unroll
        for (int bb = 0; bb < NB; bb++) {
            float mv = (bb == 0) ? m0 : (bb == 1) ? m1 : (bb == 2) ? m2 : m3;
            sm1[threadIdx.x] = mv; __syncthreads();
            for (int s = TPB/2; s > 0; s >>= 1) {
                if (threadIdx.x < s) sm1[threadIdx.x] = fmaxf(sm1[threadIdx.x], sm1[threadIdx.x+s]);
                __syncthreads();
            }
            if (threadIdx.x == 0 && sm1[0] > 0.f) atomicMax(&g_max[bb], __float_as_int(sm1[0]));
            __syncthreads();
        }
    }
    copy_range(csrc, cdst, E2, E3, t);
    gbar(); // 3

    // ---- s4: downsample + normalize ----
    for (int i = t; i < NB*HW; i += NTH) {
        int x = i % Wc;
        int y = (i / Wc) % Hc;
        int b = i / HW;
        int jy[4], jx[4]; float wy[4], wx[4];
        taps4(y, NYg, jy, wy);
        taps4(x, NXg, jx, wx);
        float acc = 0.f;
        #pragma unroll
        for (int a = 0; a < 4; a++) {
            if (wy[a] != 0.f) {
                float r = 0.f;
                #pragma unroll
                for (int c = 0; c < 4; c++)
                    if (wx[c] != 0.f)
                        r += wx[c] * g_hist[(b*NYg + jy[a])*NXg + jx[c]];
                acc += wy[a] * r;
            }
        }
        float mx = __int_as_float(g_max[b]);
        g_dm[i] = (mx > 0.f) ? acc / mx : acc;
    }
    copy_range(csrc, cdst, E3, E4, t);
    gbar(); // 4

    // ---- s5: conv1 (1->8) + stats1 (576 tiles of 592 blocks) ----
    if (bid < NB*C1*SEG1) {
        int bc = bid / SEG1, seg = bid % SEG1;   // bc = b*C1+c
        int b = bc / C1, c = bc % C1;
        const float* wp = w1 + c*9;
        const float* in = g_dm + b*HW;
        float ls = 0.f, ls2 = 0.f;
        int p0 = seg*PX1, p1 = p0 + PX1;
        for (int p = p0 + threadIdx.x; p < p1; p += TPB) {
            int x = p % Wc, y = p / Wc;
            float v = 0.f;
            #pragma unroll
            for (int dy = 0; dy < 3; dy++) {
                int yy = y + dy - 1;
                if (yy < 0 || yy >= Hc) continue;
                #pragma unroll
                for (int dx = 0; dx < 3; dx++) {
                    int xx = x + dx - 1;
                    if (xx < 0 || xx >= Wc) continue;
                    v = fmaf(__ldg(&wp[dy*3+dx]), in[yy*Wc+xx], v);
                }
            }
            g_c1[bc*HW + p] = v;
            ls += v; ls2 += v*v;
        }
        sm1[threadIdx.x] = ls; sm2[threadIdx.x] = ls2; __syncthreads();
        for (int s = TPB/2; s > 0; s >>= 1) {
            if (threadIdx.x < s) { sm1[threadIdx.x] += sm1[threadIdx.x+s]; sm2[threadIdx.x] += sm2[threadIdx.x+s]; }
            __syncthreads();
        }
        if (threadIdx.x == 0) {
            atomicAdd(&g_stats1[c],      sm1[0]);
            atomicAdd(&g_stats1[C1 + c], sm2[0]);
        }
    }
    copy_range(csrc, cdst, E4, E5, t);
    gbar(); // 5

    // ---- s6: conv2 (8->16) with inline BN1+ReLU + stats2 ----
    if (bid < NB*C2*SEG2) {
        int bc = bid / SEG2, seg = bid % SEG2;   // bc = b*C2+co
        int b = bc / C2, co = bc % C2;
        if (threadIdx.x < C1*9) ws[threadIdx.x] = w2[co*C1*9 + threadIdx.x];
        if (threadIdx.x < C1) {
            int c = threadIdx.x;
            float mean = g_stats1[c] / (float)NBN;
            float var  = g_stats1[C1+c] / (float)NBN - mean*mean;
            float s    = gamma1[c] * rsqrtf(var + 1e-3f);
            sA[c] = s; sB[c] = beta1[c] - mean*s;
        }
        __syncthreads();
        float ls = 0.f, ls2 = 0.f;
        int p0 = seg*PX2, p1 = p0 + PX2;
        for (int p = p0 + threadIdx.x; p < p1; p += TPB) {
            int x = p % Wc, y = p / Wc;
            float v = 0.f;
            #pragma unroll
            for (int ci = 0; ci < C1; ci++) {
                const float* in = g_c1 + (b*C1 + ci)*HW;
                const float* wp = ws + ci*9;
                float a = sA[ci], s0 = sB[ci];
                #pragma unroll
                for (int dy = 0; dy < 3; dy++) {
                    int yy = y + dy - 1;
                    if (yy < 0 || yy >= Hc) continue;
                    #pragma unroll
                    for (int dx = 0; dx < 3; dx++) {
                        int xx = x + dx - 1;
                        if (xx < 0 || xx >= Wc) continue;
                        float tv = fmaxf(fmaf(in[yy*Wc+xx], a, s0), 0.f);
                        v = fmaf(wp[dy*3+dx], tv, v);
                    }
                }
            }
            g_c2[bc*HW + p] = v;
            ls += v; ls2 += v*v;
        }
        sm1[threadIdx.x] = ls; sm2[threadIdx.x] = ls2; __syncthreads();
        for (int s = TPB/2; s > 0; s >>= 1) {
            if (threadIdx.x < s) { sm1[threadIdx.x] += sm1[threadIdx.x+s]; sm2[threadIdx.x] += sm2[threadIdx.x+s]; }
            __syncthreads();
        }
        if (threadIdx.x == 0) {
            atomicAdd(&g_stats2[co],      sm1[0]);
            atomicAdd(&g_stats2[C2 + co], sm2[0]);
        }
    }
    copy_range(csrc, cdst, E5, E6, t);
    gbar(); // 6 (even count -> barrier state self-restores)

    // ---- s7: BN2 + relu + scatter; zero g_hist for next launch; last copy chunk ----
    {
        if (threadIdx.x < C2) {
            int c = threadIdx.x;
            float mean = g_stats2[c] / (float)NBN;
            float var  = g_stats2[C2+c] / (float)NBN - mean*mean;
            float s    = gamma2[c] * rsqrtf(var + 1e-3f);
            sA[c] = s; sB[c] = beta2[c] - mean*s;
        }
        __syncthreads();
        for (int i = t; i < NB*C2*HW; i += NTH) {
            int hw = i % HW;
            int c  = (i / HW) % C2;
            int b  = i / (C2*HW);
            float v = fmaxf(fmaf(g_c2[i], sA[c], sB[c]), 0.f);
            out[((size_t)b*COUT + CSP + c)*HW + hw] = v;
        }
        for (int i = t; i < GTOT; i += NTH) g_hist[i] = 0.f;
    }
    copy_range(csrc, cdst, E6, COPY_N, t);
}

extern "C" void kernel_launch(void* const* d_in, const int* in_sizes, int n_in,
                              void* d_out, int out_size) {
    const float* spatial = (const float*)d_in[0];
    const float* points  = (const float*)d_in[1];
    const float* w1      = (const float*)d_in[2];
    const float* gamma1  = (const float*)d_in[3];
    const float* beta1   = (const float*)d_in[4];
    const float* w2      = (const float*)d_in[5];
    const float* gamma2  = (const float*)d_in[6];
    const float* beta2   = (const float*)d_in[7];
    float* out = (float*)d_out;
    int npts = in_sizes[1] / 5;

    k_all<<<NBLK, TPB>>>(points, npts, w1, gamma1, beta1, w2, gamma2, beta2,
                         (const float4*)spatial, (float4*)out, out);
}

// round 12
// speedup vs baseline: 1.0072x; 1.0072x over previous
#include <cuda_runtime.h>

#define NB 4
#define NXg 432
#define NYg 496
#define Hc 248
#define Wc 216
#define HW (Hc*Wc)            // 53568
#define C1 8
#define C2 16
#define COUT 400
#define CSP 384
#define KS 15
#define RAD 7
#define NBN (NB*HW)
#define GTOT (NB*NYg*NXg)     // 857088

#define NBLK 592              // = 148 SMs * 4 blocks (all co-resident)
#define TPB  256
#define NTH  (NBLK*TPB)       // 151552 threads

#define COPY_N (NB*CSP*HW/4)  // 20,570,112 float4
#define PER_B  (CSP*HW/4)     // 5,142,528
#define DSKIP  ((COUT-CSP)*HW/4)

// copy chunk boundaries per stage (cumulative float4 indices)
#define E1 2900000
#define E2 5900000
#define E3 8900000
#define E4 12100000
#define E5 15100000
#define E6 16300000
// stage 7 copies [E6, COPY_N)

// conv tiling: one (channel, segment) tile per block, 576 tiles
#define SEG1 18
#define PX1  (HW/SEG1)        // 2976
#define SEG2 9
#define PX2  (HW/SEG2)        // 5952

// scratch (device globals; zero-initialized at load)
__device__ float g_hist[GTOT];     // zeroed at end of each launch for the next
__device__ float g_tmp [GTOT];
__device__ float g_dm  [NB*HW];
__device__ float g_c1  [NB*C1*HW];
__device__ float g_c2  [NB*C2*HW];
__device__ float g_gauss[KS];
__device__ int   g_max[NB];
__device__ float g_stats1[2*C1];
__device__ float g_stats2[2*C2];
// barrier state (self-restoring: even # of barriers per launch)
__device__ int          g_cnt;
__device__ volatile int g_sense;

__device__ __forceinline__ void copy_range(const float4* __restrict__ src,
                                           float4* __restrict__ dst,
                                           int start, int end, int t) {
    for (int i = start + t; i < end; i += 4*NTH) {
        int i1 = i + NTH, i2 = i + 2*NTH, i3 = i + 3*NTH;
        bool p1 = i1 < end, p2 = i2 < end, p3 = i3 < end;
        float4 v0, v1, v2, v3;
        v0 = __ldcs(src + i);
        if (p1) v1 = __ldcs(src + i1);
        if (p2) v2 = __ldcs(src + i2);
        if (p3) v3 = __ldcs(src + i3);
        __stcs(dst + i  + (i /PER_B)*DSKIP, v0);
        if (p1) __stcs(dst + i1 + (i1/PER_B)*DSKIP, v1);
        if (p2) __stcs(dst + i2 + (i2/PER_B)*DSKIP, v2);
        if (p3) __stcs(dst + i3 + (i3/PER_B)*DSKIP, v3);
    }
}

// antialiased bilinear 2x down taps: [1,3,3,1], edge-clipped + renormalized
__device__ __forceinline__ void taps4(int i, int n, int* j, float* w) {
    const float base[4] = {1.f, 3.f, 3.f, 1.f};
    float s = 0.f;
    #pragma unroll
    for (int k = 0; k < 4; k++) {
        int jj = 2*i - 1 + k;
        j[k] = jj;
        if (jj >= 0 && jj < n) { w[k] = base[k]; s += base[k]; }
        else w[k] = 0.f;
    }
    #pragma unroll
    for (int k = 0; k < 4; k++) w[k] /= s;
}

__global__ void __launch_bounds__(TPB, 4)
k_all(const float* __restrict__ pts, int npts,
      const float* __restrict__ w1, const float* __restrict__ gamma1, const float* __restrict__ beta1,
      const float* __restrict__ w2, const float* __restrict__ gamma2, const float* __restrict__ beta2,
      const float4* __restrict__ csrc, float4* __restrict__ cdst, float* __restrict__ out)
{
    const int bid = blockIdx.x;
    const int t   = bid*TPB + threadIdx.x;

    __shared__ float sm1[TPB], sm2[TPB];
    __shared__ float ws[C1*9];
    __shared__ float sA[C2], sB[C2];
    __shared__ int   lsense;
    if (threadIdx.x == 0) lsense = 0;
    __syncthreads();

    auto gbar = [&]() {
        __syncthreads();
        if (threadIdx.x == 0) {
            int s = lsense ^ 1; lsense = s;
            __threadfence();
            if (atomicAdd(&g_cnt, 1) == NBLK - 1) {
                g_cnt = 0;
                g_sense = s;
            } else {
                while (g_sense != s) __nanosleep(64);
            }
            __threadfence();
        }
        __syncthreads();
    };

    // ---- s1: init (gauss, zero stats/max) + histogram ----
    if (t < KS) {
        const float sig = 6.25f;
        float s = 0.f;
        for (int k = 0; k < KS; k++) {
            float c = (float)(k - RAD);
            s += expf(-c*c/(2.f*sig*sig));
        }
        float c = (float)(t - RAD);
        g_gauss[t] = expf(-c*c/(2.f*sig*sig)) / s;
    }
    if (t < NB)   g_max[t] = 0;
    if (t < 2*C1) g_stats1[t] = 0.f;
    if (t < 2*C2) g_stats2[t] = 0.f;
    for (int i = t; i < npts; i += NTH) {
        const float* p = pts + (size_t)i*5;
        int b = (int)p[0];
        int x = (int)__fdiv_rn(p[1] - 0.0f,  0.16f);
        int y = (int)__fdiv_rn(p[2] + 39.68f, 0.16f);
        x = min(max(x, 0), NXg-1);
        y = min(max(y, 0), NYg-1);
        atomicAdd(&g_hist[(b*NYg + y)*NXg + x], 1.0f);   // g_hist pre-zeroed
    }
    copy_range(csrc, cdst, 0, E1, t);
    gbar(); // 1

    // ---- s2: blur x ----
    for (int i = t; i < GTOT; i += NTH) {
        int x = i % NXg;
        int row = i / NXg;
        float acc = 0.f;
        #pragma unroll
        for (int k = 0; k < KS; k++) {
            int xx = x + k - RAD;
            if (xx >= 0 && xx < NXg)
                acc += g_gauss[k] * g_hist[row*NXg + xx];
        }
        g_tmp[i] = acc;
    }
    copy_range(csrc, cdst, E1, E2, t);
    gbar(); // 2

    // ---- s3: blur y + per-batch max ----
    {
        float m0 = 0.f, m1 = 0.f, m2 = 0.f, m3 = 0.f;
        for (int i = t; i < GTOT; i += NTH) {
            int x = i % NXg;
            int y = (i / NXg) % NYg;
            int b = i / (NXg*NYg);
            float acc = 0.f;
            #pragma unroll
            for (int k = 0; k < KS; k++) {
                int yy = y + k - RAD;
                if (yy >= 0 && yy < NYg)
                    acc += g_gauss[k] * g_tmp[(b*NYg + yy)*NXg + x];
            }
            g_hist[i] = acc;
            m0 = (b == 0) ? fmaxf(m0, acc) : m0;
            m1 = (b == 1) ? fmaxf(m1, acc) : m1;
            m2 = (b == 2) ? fmaxf(m2, acc) : m2;
            m3 = (b == 3) ? fmaxf(m3, acc) : m3;
        }
        #pragma unroll
        for (int bb = 0; bb < NB; bb++) {
            float mv = (bb == 0) ? m0 : (bb == 1) ? m1 : (bb == 2) ? m2 : m3;
            sm1[threadIdx.x] = mv; __syncthreads();
            for (int s = TPB/2; s > 0; s >>= 1) {
                if (threadIdx.x < s) sm1[threadIdx.x] = fmaxf(sm1[threadIdx.x], sm1[threadIdx.x+s]);
                __syncthreads();
            }
            if (threadIdx.x == 0 && sm1[0] > 0.f) atomicMax(&g_max[bb], __float_as_int(sm1[0]));
            __syncthreads();
        }
    }
    copy_range(csrc, cdst, E2, E3, t);
    gbar(); // 3

    // ---- s4: downsample + normalize ----
    for (int i = t; i < NB*HW; i += NTH) {
        int x = i % Wc;
        int y = (i / Wc) % Hc;
        int b = i / HW;
        int jy[4], jx[4]; float wy[4], wx[4];
        taps4(y, NYg, jy, wy);
        taps4(x, NXg, jx, wx);
        float acc = 0.f;
        #pragma unroll
        for (int a = 0; a < 4; a++) {
            if (wy[a] != 0.f) {
                float r = 0.f;
                #pragma unroll
                for (int c = 0; c < 4; c++)
                    if (wx[c] != 0.f)
                        r += wx[c] * g_hist[(b*NYg + jy[a])*NXg + jx[c]];
                acc += wy[a] * r;
            }
        }
        float mx = __int_as_float(g_max[b]);
        g_dm[i] = (mx > 0.f) ? acc / mx : acc;
    }
    copy_range(csrc, cdst, E3, E4, t);
    gbar(); // 4

    // ---- s5: conv1 (1->8) + stats1 (576 tiles of 592 blocks) ----
    if (bid < NB*C1*SEG1) {
        int bc = bid / SEG1, seg = bid % SEG1;   // bc = b*C1+c
        int b = bc / C1, c = bc % C1;
        const float* wp = w1 + c*9;
        const float* in = g_dm + b*HW;
        float ls = 0.f, ls2 = 0.f;
        int p0 = seg*PX1, p1 = p0 + PX1;
        for (int p = p0 + threadIdx.x; p < p1; p += TPB) {
            int x = p % Wc, y = p / Wc;
            float v = 0.f;
            #pragma unroll
            for (int dy = 0; dy < 3; dy++) {
                int yy = y + dy - 1;
                if (yy < 0 || yy >= Hc) continue;
                #pragma unroll
                for (int dx = 0; dx < 3; dx++) {
                    int xx = x + dx - 1;
                    if (xx < 0 || xx >= Wc) continue;
                    v = fmaf(__ldg(&wp[dy*3+dx]), in[yy*Wc+xx], v);
                }
            }
            g_c1[bc*HW + p] = v;
            ls += v; ls2 += v*v;
        }
        sm1[threadIdx.x] = ls; sm2[threadIdx.x] = ls2; __syncthreads();
        for (int s = TPB/2; s > 0; s >>= 1) {
            if (threadIdx.x < s) { sm1[threadIdx.x] += sm1[threadIdx.x+s]; sm2[threadIdx.x] += sm2[threadIdx.x+s]; }
            __syncthreads();
        }
        if (threadIdx.x == 0) {
            atomicAdd(&g_stats1[c],      sm1[0]);
            atomicAdd(&g_stats1[C1 + c], sm2[0]);
        }
    }
    copy_range(csrc, cdst, E4, E5, t);
    gbar(); // 5

    // ---- s6: conv2 (8->16) with inline BN1+ReLU + stats2 ----
    if (bid < NB*C2*SEG2) {
        int bc = bid / SEG2, seg = bid % SEG2;   // bc = b*C2+co
        int b = bc / C2, co = bc % C2;
        if (threadIdx.x < C1*9) ws[threadIdx.x] = w2[co*C1*9 + threadIdx.x];
        if (threadIdx.x < C1) {
            int c = threadIdx.x;
            float mean = g_stats1[c] / (float)NBN;
            float var  = g_stats1[C1+c] / (float)NBN - mean*mean;
            float s    = gamma1[c] * rsqrtf(var + 1e-3f);
            sA[c] = s; sB[c] = beta1[c] - mean*s;
        }
        __syncthreads();
        float ls = 0.f, ls2 = 0.f;
        int p0 = seg*PX2, p1 = p0 + PX2;
        for (int p = p0 + threadIdx.x; p < p1; p += TPB) {
            int x = p % Wc, y = p / Wc;
            float v = 0.f;
            #pragma unroll
            for (int ci = 0; ci < C1; ci++) {
                const float* in = g_c1 + (b*C1 + ci)*HW;
                const float* wp = ws + ci*9;
                float a = sA[ci], s0 = sB[ci];
                #pragma unroll
                for (int dy = 0; dy < 3; dy++) {
                    int yy = y + dy - 1;
                    if (yy < 0 || yy >= Hc) continue;
                    #pragma unroll
                    for (int dx = 0; dx < 3; dx++) {
                        int xx = x + dx - 1;
                        if (xx < 0 || xx >= Wc) continue;
                        float tv = fmaxf(fmaf(in[yy*Wc+xx], a, s0), 0.f);
                        v = fmaf(wp[dy*3+dx], tv, v);
                    }
                }
            }
            g_c2[bc*HW + p] = v;
            ls += v; ls2 += v*v;
        }
        sm1[threadIdx.x] = ls; sm2[threadIdx.x] = ls2; __syncthreads();
        for (int s = TPB/2; s > 0; s >>= 1) {
            if (threadIdx.x < s) { sm1[threadIdx.x] += sm1[threadIdx.x+s]; sm2[threadIdx.x] += sm2[threadIdx.x+s]; }
            __syncthreads();
        }
        if (threadIdx.x == 0) {
            atomicAdd(&g_stats2[co],      sm1[0]);
            atomicAdd(&g_stats2[C2 + co], sm2[0]);
        }
    }
    copy_range(csrc, cdst, E5, E6, t);
    gbar(); // 6 (even count -> barrier state self-restores)

    // ---- s7: BN2 + relu + scatter; zero g_hist for next launch; last copy chunk ----
    {
        if (threadIdx.x < C2) {
            int c = threadIdx.x;
            float mean = g_stats2[c] / (float)NBN;
            float var  = g_stats2[C2+c] / (float)NBN - mean*mean;
            float s    = gamma2[c] * rsqrtf(var + 1e-3f);
            sA[c] = s; sB[c] = beta2[c] - mean*s;
        }
        __syncthreads();
        for (int i = t; i < NB*C2*HW; i += NTH) {
            int hw = i % HW;
            int c  = (i / HW) % C2;
            int b  = i / (C2*HW);
            float v = fmaxf(fmaf(g_c2[i], sA[c], sB[c]), 0.f);
            out[((size_t)b*COUT + CSP + c)*HW + hw] = v;
        }
        for (int i = t; i < GTOT; i += NTH) g_hist[i] = 0.f;
    }
    copy_range(csrc, cdst, E6, COPY_N, t);
}

extern "C" void kernel_launch(void* const* d_in, const int* in_sizes, int n_in,
                              void* d_out, int out_size) {
    const float* spatial = (const float*)d_in[0];
    const float* points  = (const float*)d_in[1];
    const float* w1      = (const float*)d_in[2];
    const float* gamma1  = (const float*)d_in[3];
    const float* beta1   = (const float*)d_in[4];
    const float* w2      = (const float*)d_in[5];
    const float* gamma2  = (const float*)d_in[6];
    const float* beta2   = (const float*)d_in[7];
    float* out = (float*)d_out;
    int npts = in_sizes[1] / 5;

    k_all<<<NBLK, TPB>>>(points, npts, w1, gamma1, beta1, w2, gamma2, beta2,
                         (const float4*)spatial, (float4*)out, out);
}

// round 17
// speedup vs baseline: 1.2291x; 1.2203x over previous
#include <cuda_runtime.h>

#define NB 4
#define NXg 432
#define NYg 496
#define Hc 248
#define Wc 216
#define HW (Hc*Wc)
#define C1 8
#define C2 16
#define COUT 400
#define CSP 384
#define KS 15
#define RAD 7
#define NBN (NB*HW)
#define GTOT (NB*NYg*NXg)

// scratch (device globals; zero-initialized at load)
__device__ float g_hist[GTOT];       // re-zeroed each launch by k_out
__device__ float g_tmp [GTOT];
__device__ float g_dm  [NB*HW];      // UNNORMALIZED down map (1/max folded into conv1)
__device__ float g_c1  [NB*C1*HW];
__device__ float g_c2  [NB*C2*HW];
__device__ float g_gauss[KS];
__device__ int   g_max[NB];
__device__ float g_stats1[2*C1];
__device__ float g_stats2[2*C2];

// ---------------- concat copy, software-pipelined through the chain ----------------
#define COPY_N  (NB*CSP*HW/4)            // 20,570,112 float4s
#define PER_B   (CSP*HW/4)               // 5,142,528
#define DSKIP   ((COUT-CSP)*HW/4)        // 214,272

// shares (sum == COPY_N); capacity D*threads >= share verified per kernel.
#define S_HIST  3000000                  // grid padded to 2930 blocks (cap 3,000,320)
#define S_BLX   3400000                  // 3348 blocks (cap 3,428,352)
#define S_BLYD  1700000                  // grid padded to 1700 blocks (cap 1,740,800)
#define S_CV1   6000000                  // 6720 blocks (cap 6,881,280)
#define S_OUT   (COPY_N - S_HIST - S_BLX - S_BLYD - S_CV1)   // 6,470,112 (cap 13.7M)
#define O_HIST  0
#define O_BLX   (O_HIST + S_HIST)
#define O_BLYD  (O_BLX + S_BLX)
#define O_CV1   (O_BLYD + S_BLYD)
#define O_OUT   (O_CV1 + S_CV1)

template<int D> struct CopyCtx { float4 v[D]; int idx[D]; };

template<int D>
__device__ __forceinline__ void copy_pro(const float4* __restrict__ src,
                                         int start, int count, CopyCtx<D>& c) {
    int tid = ((blockIdx.y*gridDim.x + blockIdx.x)*blockDim.x) + threadIdx.x;
    int nth = gridDim.x*gridDim.y*blockDim.x;
    int end = start + count;
    #pragma unroll
    for (int k = 0; k < D; k++) {
        int i = start + tid + k*nth;
        c.idx[k] = (i < end) ? i : -1;
    }
    #pragma unroll
    for (int k = 0; k < D; k++)
        if (c.idx[k] >= 0) c.v[k] = __ldcs(src + c.idx[k]);
}

template<int D>
__device__ __forceinline__ void copy_epi(float4* __restrict__ dst, const CopyCtx<D>& c) {
    #pragma unroll
    for (int k = 0; k < D; k++)
        if (c.idx[k] >= 0) {
            int b = c.idx[k] / PER_B;
            __stcs(dst + c.idx[k] + b*DSKIP, c.v[k]);
        }
}

// taps for jax.image.resize 'linear' antialias 2x down: [1,3,3,1], edge-renormalized.
// indices clamped into range; clipped taps get weight 0.
__device__ __forceinline__ void taps4(int i, int n, int* j, float* w) {
    const float base[4] = {1.f, 3.f, 3.f, 1.f};
    float s = 0.f;
    #pragma unroll
    for (int k = 0; k < 4; k++) {
        int jj = 2*i - 1 + k;
        if (jj >= 0 && jj < n) { w[k] = base[k]; s += base[k]; }
        else w[k] = 0.f;
        j[k] = min(max(jj, 0), n-1);
    }
    #pragma unroll
    for (int k = 0; k < 4; k++) w[k] /= s;
}

// ---- node 1: init (gauss/stats/max) + histogram ----
__global__ void k_hist(const float* __restrict__ pts, int n,
                       const float4* __restrict__ cs, float4* __restrict__ cd) {
    CopyCtx<4> cc; copy_pro<4>(cs, O_HIST, S_HIST, cc);
    int i = blockIdx.x*blockDim.x + threadIdx.x;
    if (i < KS) {
        const float sig = 6.25f;
        float s = 0.f;
        for (int k = 0; k < KS; k++) {
            float c = (float)(k - RAD);
            s += expf(-c*c/(2.f*sig*sig));
        }
        float c = (float)(i - RAD);
        g_gauss[i] = expf(-c*c/(2.f*sig*sig)) / s;
    }
    if (i < NB)   g_max[i] = 0;
    if (i < 2*C1) g_stats1[i] = 0.f;
    if (i < 2*C2) g_stats2[i] = 0.f;
    if (i < n) {
        const float* p = pts + (size_t)i*5;
        int b = (int)p[0];
        int x = (int)__fdiv_rn(p[1] - 0.0f,  0.16f);
        int y = (int)__fdiv_rn(p[2] + 39.68f, 0.16f);
        x = min(max(x, 0), NXg-1);
        y = min(max(y, 0), NYg-1);
        atomicAdd(&g_hist[(b*NYg + y)*NXg + x], 1.0f);   // g_hist pre-zeroed
    }
    copy_epi<4>(cd, cc);
}

// ---- node 2: blur x ----
__global__ void k_blur_x(const float4* __restrict__ cs, float4* __restrict__ cd) {
    CopyCtx<4> cc; copy_pro<4>(cs, O_BLX, S_BLX, cc);
    int i = blockIdx.x*blockDim.x + threadIdx.x;
    if (i < GTOT) {
        int x = i % NXg;
        int row = i / NXg;
        float acc = 0.f;
        #pragma unroll
        for (int k = 0; k < KS; k++) {
            int xx = x + k - RAD;
            if (xx >= 0 && xx < NXg)
                acc += g_gauss[k] * g_hist[row*NXg + xx];
        }
        g_tmp[i] = acc;
    }
    copy_epi<4>(cd, cc);
}

// ---- node 3: fused blur_y + per-batch max + downsample (unnormalized) ----
// 124 stage blocks: each owns 8 down-rows of one batch. Builds the 18 needed
// y-blurred full-res rows in smem, maxes over its 16 owned rows, emits 8x216
// down outputs. Blocks >= 124 only carry copy traffic.
#define STRIPS   31                      // 248/8 down rows per strip
#define DROWS    8
#define SROWS    18                      // 2*8+2 tap rows (+? see rlo) = 18
#define BLYD_G   1700
__global__ void k_blyd(const float4* __restrict__ cs, float4* __restrict__ cd) {
    CopyCtx<4> cc; copy_pro<4>(cs, O_BLYD, S_BLYD, cc);
    __shared__ float sh[SROWS*NXg];      // 31,104 B
    int bid = blockIdx.x;
    if (bid < NB*STRIPS) {
        int b = bid / STRIPS, s = bid % STRIPS;
        int y0 = s*DROWS;
        int rlo = 2*y0 - 1;              // rows rlo .. rlo+17 needed
        // y-blur x-blurred field into smem
        for (int idx = threadIdx.x; idx < SROWS*NXg; idx += blockDim.x) {
            int rr = idx / NXg, c = idx % NXg;
            int r = rlo + rr;
            float acc = 0.f;
            if (r >= 0 && r < NYg) {
                #pragma unroll
                for (int k = 0; k < KS; k++) {
                    int yy = r + k - RAD;
                    if (yy >= 0 && yy < NYg)
                        acc += g_gauss[k] * g_tmp[(b*NYg + yy)*NXg + c];
                }
            }
            sh[idx] = acc;
        }
        __syncthreads();
        // max over owned rows (rr = 1..16 <-> full-res rows 2y0 .. 2y0+15)
        float m = 0.f;
        for (int idx = threadIdx.x; idx < 16*NXg; idx += blockDim.x)
            m = fmaxf(m, sh[NXg + idx]);
        __shared__ float sm[256];
        sm[threadIdx.x] = m; __syncthreads();
        for (int st = 128; st > 0; st >>= 1) {
            if (threadIdx.x < st) sm[threadIdx.x] = fmaxf(sm[threadIdx.x], sm[threadIdx.x+st]);
            __syncthreads();
        }
        if (threadIdx.x == 0 && sm[0] > 0.f) atomicMax(&g_max[b], __float_as_int(sm[0]));
        // down outputs from smem (UNNORMALIZED)
        for (int o = threadIdx.x; o < DROWS*Wc; o += blockDim.x) {
            int y = y0 + o / Wc;
            int x = o % Wc;
            int jy[4], jx[4]; float wy[4], wx[4];
            taps4(y, NYg, jy, wy);
            taps4(x, NXg, jx, wx);
            float acc = 0.f;
            #pragma unroll
            for (int a = 0; a < 4; a++) {
                if (wy[a] != 0.f) {
                    const float* row = sh + (jy[a] - rlo)*NXg;
                    float r = wx[0]*row[jx[0]] + wx[1]*row[jx[1]]
                            + wx[2]*row[jx[2]] + wx[3]*row[jx[3]];
                    acc += wy[a] * r;
                }
            }
            g_dm[b*HW + y*Wc + x] = acc;
        }
    }
    copy_epi<4>(cd, cc);
}

// ---- node 4: conv1 (1->8) on dm/max (fold), + stats1 ----
__global__ void k_conv1(const float* __restrict__ w1,
                        const float4* __restrict__ cs, float4* __restrict__ cd) {
    CopyCtx<4> cc; copy_pro<4>(cs, O_CV1, S_CV1, cc);
    int bc = blockIdx.y;                 // b*C1 + c
    int b = bc / C1, c = bc % C1;
    float mx = __int_as_float(g_max[b]);
    float inv = (mx > 0.f) ? 1.f/mx : 1.f;
    int hw = blockIdx.x*blockDim.x + threadIdx.x;
    float v = 0.f;
    if (hw < HW) {
        int x = hw % Wc, y = hw / Wc;
        const float* wp = w1 + c*9;
        const float* in = g_dm + b*HW;
        #pragma unroll
        for (int dy = 0; dy < 3; dy++) {
            int yy = y + dy - 1;
            if (yy < 0 || yy >= Hc) continue;
            #pragma unroll
            for (int dx = 0; dx < 3; dx++) {
                int xx = x + dx - 1;
                if (xx < 0 || xx >= Wc) continue;
                v = fmaf(__ldg(&wp[dy*3+dx]), in[yy*Wc+xx], v);
            }
        }
        v *= inv;                        // normalization folded (conv is linear)
        g_c1[bc*HW + hw] = v;
    }
    __shared__ float s1[256], s2[256];
    float vv = (hw < HW) ? v : 0.f;
    s1[threadIdx.x] = vv; s2[threadIdx.x] = vv*vv;
    __syncthreads();
    for (int s = 128; s > 0; s >>= 1) {
        if (threadIdx.x < s) { s1[threadIdx.x] += s1[threadIdx.x+s]; s2[threadIdx.x] += s2[threadIdx.x+s]; }
        __syncthreads();
    }
    if (threadIdx.x == 0) {
        atomicAdd(&g_stats1[c], s1[0]);
        atomicAdd(&g_stats1[C1 + c], s2[0]);
    }
    copy_epi<4>(cd, cc);
}

// ---- node 5: conv2 (8->16), BN1+ReLU inline, + stats2. No copy share. ----
__global__ void k_conv2(const float* __restrict__ w2,
                        const float* __restrict__ gamma1, const float* __restrict__ beta1) {
    int bc = blockIdx.y;                 // b*C2 + co
    int b = bc / C2, co = bc % C2;
    __shared__ float ws[C1*9];
    __shared__ float sc1[C1], sh1[C1];
    if (threadIdx.x < C1*9) ws[threadIdx.x] = w2[co*C1*9 + threadIdx.x];
    if (threadIdx.x < C1) {
        int c = threadIdx.x;
        float mean = g_stats1[c] / (float)NBN;
        float var  = g_stats1[C1+c] / (float)NBN - mean*mean;
        float s    = gamma1[c] * rsqrtf(var + 1e-3f);
        sc1[c] = s; sh1[c] = beta1[c] - mean*s;
    }
    __syncthreads();
    int hw = blockIdx.x*blockDim.x + threadIdx.x;
    float v = 0.f;
    if (hw < HW) {
        int x = hw % Wc, y = hw / Wc;
        #pragma unroll
        for (int ci = 0; ci < C1; ci++) {
            const float* in = g_c1 + (b*C1 + ci)*HW;
            const float* wp = ws + ci*9;
            float a = sc1[ci], s0 = sh1[ci];
            #pragma unroll
            for (int dy = 0; dy < 3; dy++) {
                int yy = y + dy - 1;
                if (yy < 0 || yy >= Hc) continue;
                #pragma unroll
                for (int dx = 0; dx < 3; dx++) {
                    int xx = x + dx - 1;
                    if (xx < 0 || xx >= Wc) continue;
                    float t = fmaxf(fmaf(in[yy*Wc+xx], a, s0), 0.f);
                    v = fmaf(wp[dy*3+dx], t, v);
                }
            }
        }
        g_c2[bc*HW + hw] = v;
    }
    __shared__ float s1[256], s2[256];
    float vv = (hw < HW) ? v : 0.f;
    s1[threadIdx.x] = vv; s2[threadIdx.x] = vv*vv;
    __syncthreads();
    for (int s = 128; s > 0; s >>= 1) {
        if (threadIdx.x < s) { s1[threadIdx.x] += s1[threadIdx.x+s]; s2[threadIdx.x] += s2[threadIdx.x+s]; }
        __syncthreads();
    }
    if (threadIdx.x == 0) {
        atomicAdd(&g_stats2[co], s1[0]);
        atomicAdd(&g_stats2[C2 + co], s2[0]);
    }
}

// ---- node 6: BN2 + relu + scatter; zero g_hist for next launch ----
__global__ void k_out(float* __restrict__ out,
                      const float* __restrict__ gamma, const float* __restrict__ beta,
                      const float4* __restrict__ cs, float4* __restrict__ cd) {
    CopyCtx<4> cc; copy_pro<4>(cs, O_OUT, S_OUT, cc);
    __shared__ float sc[C2], sh[C2];
    if (threadIdx.x < C2) {
        int c = threadIdx.x;
        float mean = g_stats2[c] / (float)NBN;
        float var  = g_stats2[C2+c] / (float)NBN - mean*mean;
        float s    = gamma[c] * rsqrtf(var + 1e-3f);
        sc[c] = s; sh[c] = beta[c] - mean*s;
    }
    __syncthreads();
    int i = blockIdx.x*blockDim.x + threadIdx.x;
    if (i < NB*C2*HW) {
        int hw = i % HW;
        int c  = (i / HW) % C2;
        int b  = i / (C2*HW);
        float v = fmaxf(fmaf(g_c2[i], sc[c], sh[c]), 0.f);
        out[((size_t)b*COUT + CSP + c)*HW + hw] = v;
    }
    if (i < GTOT) g_hist[i] = 0.f;       // leave zeroed for next launch
    copy_epi<4>(cd, cc);
}

extern "C" void kernel_launch(void* const* d_in, const int* in_sizes, int n_in,
                              void* d_out, int out_size) {
    const float* spatial = (const float*)d_in[0];
    const float* points  = (const float*)d_in[1];
    const float* w1      = (const float*)d_in[2];
    const float* gamma1  = (const float*)d_in[3];
    const float* beta1   = (const float*)d_in[4];
    const float* w2      = (const float*)d_in[5];
    const float* gamma2  = (const float*)d_in[6];
    const float* beta2   = (const float*)d_in[7];
    float* out = (float*)d_out;
    int npts = in_sizes[1] / 5;

    const float4* cs = (const float4*)spatial;
    float4* cd = (float4*)out;

    // hist grid: at least enough threads for its copy share (4*threads >= S_HIST)
    int gh = (npts + 255)/256;
    int gmin = (S_HIST + 1023)/1024;
    if (gh < gmin) gh = gmin;

    k_hist  <<<gh, 256>>>(points, npts, cs, cd);
    k_blur_x<<<(GTOT + 255)/256, 256>>>(cs, cd);
    k_blyd  <<<BLYD_G, 256>>>(cs, cd);
    { dim3 g((HW + 255)/256, NB*C1); k_conv1<<<g, 256>>>(w1, cs, cd); }
    { dim3 g((HW + 255)/256, NB*C2); k_conv2<<<g, 256>>>(w2, gamma1, beta1); }
    k_out   <<<(NB*C2*HW + 255)/256, 256>>>(out, gamma2, beta2, cs, cd);
}